// round 11
// baseline (speedup 1.0000x reference)
#include <cuda_runtime.h>
#include <cstdint>
#include <cstddef>

// ---------------------------------------------------------------------------
// ScalEdgesRead: out[b,e,:] = (hs[b,src[e],:] + hd[b,dst[e],:]) * 1/sqrt(2)
//   hs = x @ W_src^T, hd = x @ W_dst^T     (B=2, N=50000, E=800000, D=64)
// Phase 1: node transform (small SGEMM, M=B*N, K=64, Nout=128 concat)
// Phase 2: edge gather-add-scale (memory bound)
// NOTE: src/dst arrive as int32 (JAX x64 disabled demotes jnp.int64).
// ---------------------------------------------------------------------------

#define INV_SQRT_2 0.70710678118654752440f

// Scratch: hs/hd, 64 floats per (b,n) row. M = B*N = 100000 rows here.
static constexpr int MAX_M = 100352;  // >= 100000, multiple of 64
__device__ float g_hs[(size_t)MAX_M * 64];
__device__ float g_hd[(size_t)MAX_M * 64];

// ---------------------------------------------------------------------------
// Phase 1: 64-row x 128-col tile per block, 128 threads, 8x8 outputs/thread.
// Xs: [64 rows][64 k] (16 KB), Ws: [64 k][128 j] transposed (32 KB) = 48 KB.
// ---------------------------------------------------------------------------
__global__ __launch_bounds__(128) void transform_kernel(
    const float* __restrict__ x,
    const float* __restrict__ Wsrc,   // (64, 64) row-major: W[j*64 + k]
    const float* __restrict__ Wdst,
    int M)
{
    __shared__ float Xs[64][64];
    __shared__ float Ws[64][128];     // Ws[k][j]; j<64 -> Wsrc, j>=64 -> Wdst

    const int tid  = threadIdx.x;
    const int row0 = blockIdx.x * 64;

    // Load W transposed into shared (one-time, tiny).
    for (int idx = tid; idx < 128 * 64; idx += 128) {
        int j = idx >> 6;
        int k = idx & 63;
        float v = (j < 64) ? Wsrc[j * 64 + k] : Wdst[(j - 64) * 64 + k];
        Ws[k][j] = v;
    }
    // Load X tile (float4, coalesced).
    for (int idx = tid; idx < 64 * 16; idx += 128) {
        int r  = idx >> 4;
        int c4 = idx & 15;
        int gr = row0 + r;
        float4 v = make_float4(0.f, 0.f, 0.f, 0.f);
        if (gr < M) v = reinterpret_cast<const float4*>(x)[(size_t)gr * 16 + c4];
        *reinterpret_cast<float4*>(&Xs[r][c4 * 4]) = v;
    }
    __syncthreads();

    const int tx = tid & 15;          // column group: 16 groups of 8 cols
    const int ty = tid >> 4;          // row group:     8 groups of 8 rows
    const int rb = ty * 8;
    const int cb = tx * 8;

    float acc[8][8];
#pragma unroll
    for (int i = 0; i < 8; ++i)
#pragma unroll
        for (int j = 0; j < 8; ++j) acc[i][j] = 0.f;

#pragma unroll 4
    for (int k = 0; k < 64; ++k) {
        float a[8];
#pragma unroll
        for (int i = 0; i < 8; ++i) a[i] = Xs[rb + i][k];
        float4 b0 = *reinterpret_cast<const float4*>(&Ws[k][cb]);
        float4 b1 = *reinterpret_cast<const float4*>(&Ws[k][cb + 4]);
        float bv[8] = {b0.x, b0.y, b0.z, b0.w, b1.x, b1.y, b1.z, b1.w};
#pragma unroll
        for (int i = 0; i < 8; ++i)
#pragma unroll
            for (int j = 0; j < 8; ++j)
                acc[i][j] = fmaf(a[i], bv[j], acc[i][j]);
    }

    // Write: tx<8 -> hs cols [cb, cb+8), tx>=8 -> hd cols [cb-64, cb-56)
    float* outbuf = (tx < 8) ? g_hs : g_hd;
    const int ccol = (tx < 8) ? cb : (cb - 64);
#pragma unroll
    for (int i = 0; i < 8; ++i) {
        int gr = row0 + rb + i;
        if (gr < M) {
            float* p = outbuf + (size_t)gr * 64 + ccol;
            *reinterpret_cast<float4*>(p)     = make_float4(acc[i][0], acc[i][1], acc[i][2], acc[i][3]);
            *reinterpret_cast<float4*>(p + 4) = make_float4(acc[i][4], acc[i][5], acc[i][6], acc[i][7]);
        }
    }
}

// ---------------------------------------------------------------------------
// Phase 2: one 16-thread group per output row (b,e); float4 per thread.
// 256 threads/block = 16 rows/block. Indices staged through shared.
// ---------------------------------------------------------------------------
__global__ __launch_bounds__(256) void gather_kernel(
    const int* __restrict__ src,
    const int* __restrict__ dst,
    float* __restrict__ out,
    int E, int N, long long total_rows)
{
    __shared__ int s_idx[2][16];      // [0]=src node, [1]=dst node per row

    const long long row0 = (long long)blockIdx.x * 16;
    const int t = threadIdx.x;

    if (t < 32) {
        int i = t & 15;
        long long row = row0 + i;
        if (row < total_rows) {
            int e = (int)(row % (long long)E);
            s_idx[t >> 4][i] = (t < 16) ? src[e] : dst[e];
        }
    }
    __syncthreads();

    const int i = t >> 4;             // row within block
    const int c = t & 15;             // float4 chunk within row (D=64 -> 16 f4)
    const long long row = row0 + i;
    if (row >= total_rows) return;

    const int b = (int)(row / (long long)E);
    const int sn = s_idx[0][i];
    const int dn = s_idx[1][i];

    const float4* hs4 = reinterpret_cast<const float4*>(g_hs);
    const float4* hd4 = reinterpret_cast<const float4*>(g_hd);

    float4 a = hs4[((size_t)b * N + sn) * 16 + c];
    float4 d = hd4[((size_t)b * N + dn) * 16 + c];

    float4 o;
    o.x = (a.x + d.x) * INV_SQRT_2;
    o.y = (a.y + d.y) * INV_SQRT_2;
    o.z = (a.z + d.z) * INV_SQRT_2;
    o.w = (a.w + d.w) * INV_SQRT_2;

    // Streaming store: evict-first so hs/hd stay L2-resident.
    __stcs(reinterpret_cast<float4*>(out) + (size_t)row * 16 + c, o);
}

// ---------------------------------------------------------------------------
extern "C" void kernel_launch(void* const* d_in, const int* in_sizes, int n_in,
                              void* d_out, int out_size)
{
    const float* x    = (const float*)d_in[0];   // (B, N, 64)
    const int*   src  = (const int*)d_in[1];     // (E,) int32
    const int*   dst  = (const int*)d_in[2];     // (E,) int32
    const float* Wsrc = (const float*)d_in[3];   // (64, 64)
    const float* Wdst = (const float*)d_in[4];   // (64, 64)

    const int D = 64;
    const int E = in_sizes[1];
    const int M = in_sizes[0] / D;                        // B*N
    const long long total_rows = (long long)out_size / D; // B*E
    const int B = (int)(total_rows / E);
    const int N = M / B;

    // Phase 1: node transform
    {
        int grid = (M + 63) / 64;
        transform_kernel<<<grid, 128>>>(x, Wsrc, Wdst, M);
    }
    // Phase 2: edge gather
    {
        long long blocks = (total_rows + 15) / 16;
        gather_kernel<<<(unsigned)blocks, 256>>>(src, dst, (float*)d_out, E, N, total_rows);
    }
}